// round 4
// baseline (speedup 1.0000x reference)
#include <cuda_runtime.h>
#include <math.h>
#include <stdint.h>

#define SQ   2048
#define EMB  1024
#define NH   16
#define HDIM 64
#define NB   2
#define MR   (NB * SQ)          /* 4096 rows of the flattened [B*S, EMB] matrix */

// ---------------------------------------------------------------------------
// Scratch (device globals; no runtime allocation allowed)
// ---------------------------------------------------------------------------
static __device__ float g_Q [MR * EMB];                 // 16 MB
static __device__ float g_K [MR * EMB];                 // 16 MB
static __device__ float g_V [MR * EMB];                 // 16 MB
static __device__ float g_AO[MR * EMB];                 // 16 MB
static __device__ float g_SC[134217728];                // 512 MB fallback scratch

// ---------------------------------------------------------------------------
// NT SGEMM: C[M,N] = A[M,K] * B[N,K]^T  (row-major, lda=ldb=ldc=1024, K=1024).
// Tile 128x128, BK=8, 256 threads, 8x8 per thread.  grid = (N/128, M/128)
// ---------------------------------------------------------------------------
__global__ __launch_bounds__(256, 2)
void sgemm_nt(const float* __restrict__ A, const float* __restrict__ B,
              float* __restrict__ C)
{
    __shared__ float As[8][132];
    __shared__ float Bs[8][132];

    const int bm  = blockIdx.y * 128;
    const int bn  = blockIdx.x * 128;
    const int tid = threadIdx.x;

    const int lrow = tid >> 1;          // 0..127
    const int lq   = (tid & 1) * 4;     // 0 or 4
    const int tm   = (tid >> 4) * 8;    // 0..120
    const int tn   = (tid & 15) * 8;    // 0..120

    const float* Ap = A + (size_t)(bm + lrow) * EMB + lq;
    const float* Bp = B + (size_t)(bn + lrow) * EMB + lq;

    float acc[8][8] = {};

    for (int k0 = 0; k0 < EMB; k0 += 8) {
        float4 a4 = *(const float4*)(Ap + k0);
        float4 b4 = *(const float4*)(Bp + k0);
        As[lq + 0][lrow] = a4.x; As[lq + 1][lrow] = a4.y;
        As[lq + 2][lrow] = a4.z; As[lq + 3][lrow] = a4.w;
        Bs[lq + 0][lrow] = b4.x; Bs[lq + 1][lrow] = b4.y;
        Bs[lq + 2][lrow] = b4.z; Bs[lq + 3][lrow] = b4.w;
        __syncthreads();
#pragma unroll
        for (int kk = 0; kk < 8; kk++) {
            float a[8], b[8];
#pragma unroll
            for (int i = 0; i < 8; i++) a[i] = As[kk][tm + i];
#pragma unroll
            for (int j = 0; j < 8; j++) b[j] = Bs[kk][tn + j];
#pragma unroll
            for (int i = 0; i < 8; i++)
#pragma unroll
                for (int j = 0; j < 8; j++) acc[i][j] += a[i] * b[j];
        }
        __syncthreads();
    }

#pragma unroll
    for (int i = 0; i < 8; i++) {
        float* cp = C + (size_t)(bm + tm + i) * EMB + bn + tn;
        *(float4*)(cp)     = make_float4(acc[i][0], acc[i][1], acc[i][2], acc[i][3]);
        *(float4*)(cp + 4) = make_float4(acc[i][4], acc[i][5], acc[i][6], acc[i][7]);
    }
}

// ---------------------------------------------------------------------------
// Scores: per (b,h)  Sc[q,k] = 0.125 * dot(Qh[q], Kh[k]),  K = 64.
// Fully-masked tiles (bn > bm+127) are skipped entirely.
// grid = (SQ/128, SQ/128, B*H)
// ---------------------------------------------------------------------------
__global__ __launch_bounds__(256, 2)
void scores_kernel(const float* __restrict__ Q, const float* __restrict__ Km,
                   float* __restrict__ Sc)
{
    const int z  = blockIdx.z;
    const int bm = blockIdx.y * 128;
    const int bn = blockIdx.x * 128;
    if (bn > bm + 127) return;                 // fully above diagonal -> masked

    const int b = z >> 4, h = z & 15;
    const float* A  = Q  + (size_t)b * SQ * EMB + h * HDIM;
    const float* Bp = Km + (size_t)b * SQ * EMB + h * HDIM;
    float*       C  = Sc + (size_t)z * SQ * SQ;

    __shared__ float As[8][132];
    __shared__ float Bs[8][132];

    const int tid  = threadIdx.x;
    const int lrow = tid >> 1;
    const int lq   = (tid & 1) * 4;
    const int tm   = (tid >> 4) * 8;
    const int tn   = (tid & 15) * 8;

    const float* Ap2 = A  + (size_t)(bm + lrow) * EMB + lq;
    const float* Bp2 = Bp + (size_t)(bn + lrow) * EMB + lq;

    float acc[8][8] = {};

    for (int k0 = 0; k0 < HDIM; k0 += 8) {
        float4 a4 = *(const float4*)(Ap2 + k0);
        float4 b4 = *(const float4*)(Bp2 + k0);
        As[lq + 0][lrow] = a4.x; As[lq + 1][lrow] = a4.y;
        As[lq + 2][lrow] = a4.z; As[lq + 3][lrow] = a4.w;
        Bs[lq + 0][lrow] = b4.x; Bs[lq + 1][lrow] = b4.y;
        Bs[lq + 2][lrow] = b4.z; Bs[lq + 3][lrow] = b4.w;
        __syncthreads();
#pragma unroll
        for (int kk = 0; kk < 8; kk++) {
            float a[8], b[8];
#pragma unroll
            for (int i = 0; i < 8; i++) a[i] = As[kk][tm + i];
#pragma unroll
            for (int j = 0; j < 8; j++) b[j] = Bs[kk][tn + j];
#pragma unroll
            for (int i = 0; i < 8; i++)
#pragma unroll
                for (int j = 0; j < 8; j++) acc[i][j] += a[i] * b[j];
        }
        __syncthreads();
    }

    const float alpha = 0.125f;   // 1/sqrt(64)
#pragma unroll
    for (int i = 0; i < 8; i++) {
        float* cp = C + (size_t)(bm + tm + i) * SQ + bn + tn;
        *(float4*)(cp)     = make_float4(acc[i][0] * alpha, acc[i][1] * alpha,
                                         acc[i][2] * alpha, acc[i][3] * alpha);
        *(float4*)(cp + 4) = make_float4(acc[i][4] * alpha, acc[i][5] * alpha,
                                         acc[i][6] * alpha, acc[i][7] * alpha);
    }
}

// ---------------------------------------------------------------------------
// Causal softmax, IN-PLACE capable (reads row into registers first).
// One block (256 thr) per row, 8 elems/thread: one gmem read + one write.
// Writes exact zeros above the diagonal. grid = (SQ, B*H)
// ---------------------------------------------------------------------------
__global__ __launch_bounds__(256)
void softmax_kernel(const float* __restrict__ Sraw, float* __restrict__ Wout)
{
    const int q  = blockIdx.x;
    const int bh = blockIdx.y;
    const size_t base = ((size_t)bh * SQ + q) * SQ;
    const float* in  = Sraw + base;
    float*       out = Wout + base;
    const int valid = q + 1;
    const int tid = threadIdx.x;

    float x[8];
    float mx = -INFINITY;
#pragma unroll
    for (int i = 0; i < 8; i++) {
        const int k = tid + i * 256;
        x[i] = (k < valid) ? in[k] : -INFINITY;
        mx = fmaxf(mx, x[i]);
    }

    __shared__ float redm[8];
    __shared__ float reds[8];
#pragma unroll
    for (int o = 16; o > 0; o >>= 1) mx = fmaxf(mx, __shfl_xor_sync(0xffffffffu, mx, o));
    if ((tid & 31) == 0) redm[tid >> 5] = mx;
    __syncthreads();
    float m = redm[0];
#pragma unroll
    for (int w = 1; w < 8; w++) m = fmaxf(m, redm[w]);

    float s = 0.f;
#pragma unroll
    for (int i = 0; i < 8; i++) {
        const int k = tid + i * 256;
        x[i] = (k < valid) ? __expf(x[i] - m) : 0.f;
        s += x[i];
    }
#pragma unroll
    for (int o = 16; o > 0; o >>= 1) s += __shfl_xor_sync(0xffffffffu, s, o);
    if ((tid & 31) == 0) reds[tid >> 5] = s;
    __syncthreads();
    float st = reds[0];
#pragma unroll
    for (int w = 1; w < 8; w++) st += reds[w];

    const float inv = 1.f / st;
#pragma unroll
    for (int i = 0; i < 8; i++) out[tid + i * 256] = x[i] * inv;
}

// ---------------------------------------------------------------------------
// AV: per (b,h)  O[q,d] = sum_k W[q,k] * Vh[k,d].  Block tile 128(M) x 64(N),
// BK=16, 256 threads, 8x4 per thread.  k-loop clamped at the diagonal.
// grid = (SQ/128, B*H)
// ---------------------------------------------------------------------------
__global__ __launch_bounds__(256, 2)
void av_kernel(const float* __restrict__ W, const float* __restrict__ V,
               float* __restrict__ O)
{
    const int bh = blockIdx.y;
    const int b = bh >> 4, h = bh & 15;
    const int m0 = blockIdx.x * 128;

    const float* Wp = W + (size_t)bh * SQ * SQ;
    const float* Vp = V + (size_t)b * SQ * EMB + h * HDIM;
    float*       Op = O + (size_t)b * SQ * EMB + h * HDIM;

    __shared__ float As[16][133];   // transposed W tile: As[k][m]
    __shared__ float Bs[16][68];    // V tile: Bs[k][d]

    const int tid = threadIdx.x;
    const int tm = (tid >> 4) * 8;   // 0..120
    const int tn = (tid & 15) * 4;   // 0..60

    float acc[8][4] = {};

    const int kmax = (m0 + 128 < SQ) ? (m0 + 128) : SQ;
    for (int k0 = 0; k0 < kmax; k0 += 16) {
#pragma unroll
        for (int r = 0; r < 2; r++) {
            const int t    = tid + r * 256;
            const int row  = t >> 2;            // 0..127
            const int quad = (t & 3) * 4;       // 0,4,8,12
            float4 w4 = *(const float4*)(Wp + (size_t)(m0 + row) * SQ + k0 + quad);
            As[quad + 0][row] = w4.x; As[quad + 1][row] = w4.y;
            As[quad + 2][row] = w4.z; As[quad + 3][row] = w4.w;
        }
        {
            const int vr = tid >> 4;            // 0..15
            const int vc = (tid & 15) * 4;      // 0..60
            float4 v4 = *(const float4*)(Vp + (size_t)(k0 + vr) * EMB + vc);
            Bs[vr][vc + 0] = v4.x; Bs[vr][vc + 1] = v4.y;
            Bs[vr][vc + 2] = v4.z; Bs[vr][vc + 3] = v4.w;
        }
        __syncthreads();
#pragma unroll
        for (int kk = 0; kk < 16; kk++) {
            float bv[4];
#pragma unroll
            for (int j = 0; j < 4; j++) bv[j] = Bs[kk][tn + j];
#pragma unroll
            for (int i = 0; i < 8; i++) {
                const float a = As[kk][tm + i];
#pragma unroll
                for (int j = 0; j < 4; j++) acc[i][j] += a * bv[j];
            }
        }
        __syncthreads();
    }

#pragma unroll
    for (int i = 0; i < 8; i++) {
        *(float4*)(Op + (size_t)(m0 + tm + i) * EMB + tn) =
            make_float4(acc[i][0], acc[i][1], acc[i][2], acc[i][3]);
    }
}

// ---------------------------------------------------------------------------
// Launch
// ---------------------------------------------------------------------------
extern "C" void kernel_launch(void* const* d_in, const int* in_sizes, int n_in,
                              void* d_out, int out_size)
{
    const float* X  = (const float*)d_in[0];   // query  [B,S,E]
    // d_in[1] = key (unused: self-attention), d_in[2] = mask (implicit causal)
    const float* Wq = (const float*)d_in[3];
    const float* Wk = (const float*)d_in[4];
    const float* Wv = (const float*)d_in[5];
    const float* Wo = (const float*)d_in[6];
    float* out = (float*)d_out;

    float *Qp, *Kp, *Vp, *AOp, *SCp;
    cudaGetSymbolAddress((void**)&Qp,  g_Q);
    cudaGetSymbolAddress((void**)&Kp,  g_K);
    cudaGetSymbolAddress((void**)&Vp,  g_V);
    cudaGetSymbolAddress((void**)&AOp, g_AO);
    cudaGetSymbolAddress((void**)&SCp, g_SC);

    const size_t n_attn = (size_t)MR * EMB;          // 4,194,304
    const size_t n_w    = (size_t)NB * NH * SQ * SQ; // 134,217,728

    float* attndst;
    float* wdst;
    if ((size_t)out_size >= n_attn + n_w) { attndst = out; wdst = out + n_attn; }
    else if ((size_t)out_size == n_w)     { attndst = nullptr; wdst = out; }
    else                                  { attndst = out; wdst = SCp; }

    const dim3 blk(256);

    // Q/K/V projections: [4096,1024] x [1024,1024]^T
    sgemm_nt<<<dim3(EMB / 128, MR / 128), blk>>>(X, Wq, Qp);
    sgemm_nt<<<dim3(EMB / 128, MR / 128), blk>>>(X, Wk, Kp);
    sgemm_nt<<<dim3(EMB / 128, MR / 128), blk>>>(X, Wv, Vp);

    // raw scores straight into the weights destination (causal tiles only)
    scores_kernel<<<dim3(SQ / 128, SQ / 128, NB * NH), blk>>>(Qp, Kp, wdst);

    // softmax IN-PLACE on wdst (reads row to registers, then overwrites;
    // also zero-fills the masked upper triangle)
    softmax_kernel<<<dim3(SQ, NB * NH), blk>>>(wdst, wdst);

    if (attndst) {
        // attn_out = W @ V per head
        av_kernel<<<dim3(SQ / 128, NB * NH), blk>>>(wdst, Vp, AOp);
        // final projection -> d_out
        sgemm_nt<<<dim3(EMB / 128, MR / 128), blk>>>(AOp, Wo, attndst);
    }
}

// round 10
// speedup vs baseline: 1.3926x; 1.3926x over previous
#include <cuda_runtime.h>
#include <cuda_bf16.h>
#include <math.h>
#include <stdint.h>

#define SQ   2048
#define EMB  1024
#define NH   16
#define HDIM 64
#define NB   2
#define MR   (NB * SQ)          /* 4096 rows of the flattened [B*S, EMB] matrix */

// ---------------------------------------------------------------------------
// Scratch (device globals; no runtime allocation allowed)
// ---------------------------------------------------------------------------
static __device__ float g_Q [MR * EMB];                 // 16 MB
static __device__ float g_K [MR * EMB];                 // 16 MB
static __device__ float g_V [MR * EMB];                 // 16 MB
static __device__ float g_AO[MR * EMB];                 // 16 MB
static __device__ float g_SC[134217728];                // 512 MB fallback scratch

// bf16 hi/lo split operands for 3xBF16 tensor-core GEMMs
static __device__ __nv_bfloat16 g_Xhi [MR * EMB];       // 8 MB
static __device__ __nv_bfloat16 g_Xlo [MR * EMB];
static __device__ __nv_bfloat16 g_AOhi[MR * EMB];
static __device__ __nv_bfloat16 g_AOlo[MR * EMB];
static __device__ __nv_bfloat16 g_Whi [4 * EMB * EMB];  // Wq,Wk,Wv,Wo hi
static __device__ __nv_bfloat16 g_Wlo [4 * EMB * EMB];  // Wq,Wk,Wv,Wo lo

// ---------------------------------------------------------------------------
// Tensor-core primitives available on plain sm_103 (no 'a' features):
// ldmatrix (sm_75+) + mma.sync bf16 (sm_80+)
// ---------------------------------------------------------------------------
__device__ __forceinline__ uint32_t smem_u32(const void* p) {
    uint32_t a;
    asm("{ .reg .u64 t; cvta.to.shared.u64 t, %1; cvt.u32.u64 %0, t; }"
        : "=r"(a) : "l"(p));
    return a;
}
__device__ __forceinline__ void ldsm4(uint32_t* r, uint32_t addr) {
    asm volatile("ldmatrix.sync.aligned.m8n8.x4.shared.b16 {%0,%1,%2,%3}, [%4];"
                 : "=r"(r[0]), "=r"(r[1]), "=r"(r[2]), "=r"(r[3]) : "r"(addr));
}
__device__ __forceinline__ void mma_bf16(float* c, const uint32_t* a, const uint32_t* b) {
    asm volatile(
        "mma.sync.aligned.m16n8k16.row.col.f32.bf16.bf16.f32 "
        "{%0,%1,%2,%3}, {%4,%5,%6,%7}, {%8,%9}, {%0,%1,%2,%3};"
        : "+f"(c[0]), "+f"(c[1]), "+f"(c[2]), "+f"(c[3])
        : "r"(a[0]), "r"(a[1]), "r"(a[2]), "r"(a[3]), "r"(b[0]), "r"(b[1]));
}

// ---------------------------------------------------------------------------
// fp32 -> (hi, lo) bf16 split.  n4 = n/4 float4 elements.
// ---------------------------------------------------------------------------
__global__ __launch_bounds__(256)
void split_kernel(const float* __restrict__ x, __nv_bfloat16* __restrict__ hi,
                  __nv_bfloat16* __restrict__ lo, int n4)
{
    int i = blockIdx.x * blockDim.x + threadIdx.x;
    if (i >= n4) return;
    float4 v = ((const float4*)x)[i];
    __nv_bfloat16 h0 = __float2bfloat16(v.x);
    __nv_bfloat16 h1 = __float2bfloat16(v.y);
    __nv_bfloat16 h2 = __float2bfloat16(v.z);
    __nv_bfloat16 h3 = __float2bfloat16(v.w);
    __nv_bfloat16 l0 = __float2bfloat16(v.x - __bfloat162float(h0));
    __nv_bfloat16 l1 = __float2bfloat16(v.y - __bfloat162float(h1));
    __nv_bfloat16 l2 = __float2bfloat16(v.z - __bfloat162float(h2));
    __nv_bfloat16 l3 = __float2bfloat16(v.w - __bfloat162float(h3));
    union { __nv_bfloat162 b[2]; uint2 u; } H, L;
    H.b[0] = __halves2bfloat162(h0, h1); H.b[1] = __halves2bfloat162(h2, h3);
    L.b[0] = __halves2bfloat162(l0, l1); L.b[1] = __halves2bfloat162(l2, l3);
    *(uint2*)(hi + 4 * (size_t)i) = H.u;
    *(uint2*)(lo + 4 * (size_t)i) = L.u;
}

// ---------------------------------------------------------------------------
// 3xBF16 NT GEMM on mma.sync:  C[M,1024] = A[M,1024] * B[1024,1024]^T (fp32).
// Block 128x128, 8 warps (2x4), warp tile 64x32, BK=32.
// Per k16 step: hh + hl + lh terms accumulated in fp32.
// grid = (1024/128 = 8, M/128), 256 threads.
// ---------------------------------------------------------------------------
#define LDS 40   /* bf16 row stride: 80B -> conflict-free ldmatrix */

__global__ __launch_bounds__(256, 1)
void mma_gemm(const __nv_bfloat16* __restrict__ Ahi, const __nv_bfloat16* __restrict__ Alo,
              const __nv_bfloat16* __restrict__ Bhi, const __nv_bfloat16* __restrict__ Blo,
              float* __restrict__ C)
{
    __shared__ __nv_bfloat16 Ah[128][LDS];
    __shared__ __nv_bfloat16 Al[128][LDS];
    __shared__ __nv_bfloat16 Bh[128][LDS];
    __shared__ __nv_bfloat16 Bl[128][LDS];

    const int tid  = threadIdx.x;
    const int wid  = tid >> 5;
    const int lane = tid & 31;
    const int bm   = blockIdx.y * 128;
    const int bn   = blockIdx.x * 128;
    const int wm   = (wid >> 2) * 64;    // warp row: 0 or 64
    const int wn   = (wid & 3) * 32;     // warp col: 0,32,64,96

    float acc[4][4][4] = {};             // [m-tile][n-tile][frag]

    for (int k0 = 0; k0 < EMB; k0 += 32) {
        // global -> smem: 128 rows x 32 bf16 per operand, uint4 per thread x2
#pragma unroll
        for (int i = 0; i < 2; i++) {
            const int idx = tid + i * 256;      // 0..511
            const int row = idx >> 2;           // 0..127
            const int c8  = (idx & 3) * 8;      // 0,8,16,24
            const size_t ga = (size_t)(bm + row) * EMB + k0 + c8;
            const size_t gb = (size_t)(bn + row) * EMB + k0 + c8;
            *(uint4*)&Ah[row][c8] = *(const uint4*)(Ahi + ga);
            *(uint4*)&Al[row][c8] = *(const uint4*)(Alo + ga);
            *(uint4*)&Bh[row][c8] = *(const uint4*)(Bhi + gb);
            *(uint4*)&Bl[row][c8] = *(const uint4*)(Blo + gb);
        }
        __syncthreads();

#pragma unroll
        for (int ks = 0; ks < 32; ks += 16) {
            uint32_t ah[4][4], al[4][4], bh[4][2], bl[4][2];
            // A fragments (row-major m16k16): x4 = {m0-7/k0-7, m8-15/k0-7, m0-7/k8-15, m8-15/k8-15}
#pragma unroll
            for (int mt = 0; mt < 4; mt++) {
                const int row = wm + mt * 16 + (lane & 15);
                const int col = ks + ((lane >> 4) << 3);
                ldsm4(ah[mt], smem_u32(&Ah[row][col]));
                ldsm4(al[mt], smem_u32(&Al[row][col]));
            }
            // B fragments (col-major k16n8 == rows of Bs[n][k]): one x4 covers 2 n-tiles
#pragma unroll
            for (int np = 0; np < 2; np++) {
                const int nrow = wn + np * 16 + (lane & 7) + ((lane & 16) ? 8 : 0);
                const int col  = ks + ((lane & 8) ? 8 : 0);
                uint32_t t[4];
                ldsm4(t, smem_u32(&Bh[nrow][col]));
                bh[np * 2 + 0][0] = t[0]; bh[np * 2 + 0][1] = t[1];
                bh[np * 2 + 1][0] = t[2]; bh[np * 2 + 1][1] = t[3];
                ldsm4(t, smem_u32(&Bl[nrow][col]));
                bl[np * 2 + 0][0] = t[0]; bl[np * 2 + 0][1] = t[1];
                bl[np * 2 + 1][0] = t[2]; bl[np * 2 + 1][1] = t[3];
            }
#pragma unroll
            for (int mt = 0; mt < 4; mt++)
#pragma unroll
                for (int nt = 0; nt < 4; nt++) {
                    mma_bf16(acc[mt][nt], ah[mt], bh[nt]);
                    mma_bf16(acc[mt][nt], ah[mt], bl[nt]);
                    mma_bf16(acc[mt][nt], al[mt], bh[nt]);
                }
        }
        __syncthreads();
    }

    // epilogue: D frag -> C (2 rows x 2 cols per thread per tile)
#pragma unroll
    for (int mt = 0; mt < 4; mt++) {
#pragma unroll
        for (int nt = 0; nt < 4; nt++) {
            const int r0 = bm + wm + mt * 16 + (lane >> 2);
            const int cc = bn + wn + nt * 8 + (lane & 3) * 2;
            *(float2*)&C[(size_t)r0 * EMB + cc] =
                make_float2(acc[mt][nt][0], acc[mt][nt][1]);
            *(float2*)&C[(size_t)(r0 + 8) * EMB + cc] =
                make_float2(acc[mt][nt][2], acc[mt][nt][3]);
        }
    }
}

// ---------------------------------------------------------------------------
// Scores: per (b,h)  Sc[q,k] = 0.125 * dot(Qh[q], Kh[k]),  K = 64.  (fp32)
// Fully-masked tiles skipped.  grid = (SQ/128, SQ/128, B*H)
// ---------------------------------------------------------------------------
__global__ __launch_bounds__(256, 2)
void scores_kernel(const float* __restrict__ Q, const float* __restrict__ Km,
                   float* __restrict__ Sc)
{
    const int z  = blockIdx.z;
    const int bm = blockIdx.y * 128;
    const int bn = blockIdx.x * 128;
    if (bn > bm + 127) return;

    const int b = z >> 4, h = z & 15;
    const float* A  = Q  + (size_t)b * SQ * EMB + h * HDIM;
    const float* Bp = Km + (size_t)b * SQ * EMB + h * HDIM;
    float*       C  = Sc + (size_t)z * SQ * SQ;

    __shared__ float As[8][132];
    __shared__ float Bs[8][132];

    const int tid  = threadIdx.x;
    const int lrow = tid >> 1;
    const int lq   = (tid & 1) * 4;
    const int tm   = (tid >> 4) * 8;
    const int tn   = (tid & 15) * 8;

    const float* Ap2 = A  + (size_t)(bm + lrow) * EMB + lq;
    const float* Bp2 = Bp + (size_t)(bn + lrow) * EMB + lq;

    float acc[8][8] = {};

    for (int k0 = 0; k0 < HDIM; k0 += 8) {
        float4 a4 = *(const float4*)(Ap2 + k0);
        float4 b4 = *(const float4*)(Bp2 + k0);
        As[lq + 0][lrow] = a4.x; As[lq + 1][lrow] = a4.y;
        As[lq + 2][lrow] = a4.z; As[lq + 3][lrow] = a4.w;
        Bs[lq + 0][lrow] = b4.x; Bs[lq + 1][lrow] = b4.y;
        Bs[lq + 2][lrow] = b4.z; Bs[lq + 3][lrow] = b4.w;
        __syncthreads();
#pragma unroll
        for (int kk = 0; kk < 8; kk++) {
            float a[8], b[8];
#pragma unroll
            for (int i = 0; i < 8; i++) a[i] = As[kk][tm + i];
#pragma unroll
            for (int j = 0; j < 8; j++) b[j] = Bs[kk][tn + j];
#pragma unroll
            for (int i = 0; i < 8; i++)
#pragma unroll
                for (int j = 0; j < 8; j++) acc[i][j] += a[i] * b[j];
        }
        __syncthreads();
    }

    const float alpha = 0.125f;
#pragma unroll
    for (int i = 0; i < 8; i++) {
        float* cp = C + (size_t)(bm + tm + i) * SQ + bn + tn;
        *(float4*)(cp)     = make_float4(acc[i][0] * alpha, acc[i][1] * alpha,
                                         acc[i][2] * alpha, acc[i][3] * alpha);
        *(float4*)(cp + 4) = make_float4(acc[i][4] * alpha, acc[i][5] * alpha,
                                         acc[i][6] * alpha, acc[i][7] * alpha);
    }
}

// ---------------------------------------------------------------------------
// Causal softmax, in-place capable.  grid = (SQ, B*H)
// ---------------------------------------------------------------------------
__global__ __launch_bounds__(256)
void softmax_kernel(const float* __restrict__ Sraw, float* __restrict__ Wout)
{
    const int q  = blockIdx.x;
    const int bh = blockIdx.y;
    const size_t base = ((size_t)bh * SQ + q) * SQ;
    const float* in  = Sraw + base;
    float*       out = Wout + base;
    const int valid = q + 1;
    const int tid = threadIdx.x;

    float x[8];
    float mx = -INFINITY;
#pragma unroll
    for (int i = 0; i < 8; i++) {
        const int k = tid + i * 256;
        x[i] = (k < valid) ? in[k] : -INFINITY;
        mx = fmaxf(mx, x[i]);
    }

    __shared__ float redm[8];
    __shared__ float reds[8];
#pragma unroll
    for (int o = 16; o > 0; o >>= 1) mx = fmaxf(mx, __shfl_xor_sync(0xffffffffu, mx, o));
    if ((tid & 31) == 0) redm[tid >> 5] = mx;
    __syncthreads();
    float m = redm[0];
#pragma unroll
    for (int w = 1; w < 8; w++) m = fmaxf(m, redm[w]);

    float s = 0.f;
#pragma unroll
    for (int i = 0; i < 8; i++) {
        const int k = tid + i * 256;
        x[i] = (k < valid) ? __expf(x[i] - m) : 0.f;
        s += x[i];
    }
#pragma unroll
    for (int o = 16; o > 0; o >>= 1) s += __shfl_xor_sync(0xffffffffu, s, o);
    if ((tid & 31) == 0) reds[tid >> 5] = s;
    __syncthreads();
    float st = reds[0];
#pragma unroll
    for (int w = 1; w < 8; w++) st += reds[w];

    const float inv = 1.f / st;
#pragma unroll
    for (int i = 0; i < 8; i++) out[tid + i * 256] = x[i] * inv;
}

// ---------------------------------------------------------------------------
// AV: per (b,h)  O[q,d] = sum_k W[q,k] * Vh[k,d].  128x64 tile, BK=16.
// grid = (SQ/128, B*H)
// ---------------------------------------------------------------------------
__global__ __launch_bounds__(256, 2)
void av_kernel(const float* __restrict__ W, const float* __restrict__ V,
               float* __restrict__ O)
{
    const int bh = blockIdx.y;
    const int b = bh >> 4, h = bh & 15;
    const int m0 = blockIdx.x * 128;

    const float* Wp = W + (size_t)bh * SQ * SQ;
    const float* Vp = V + (size_t)b * SQ * EMB + h * HDIM;
    float*       Op = O + (size_t)b * SQ * EMB + h * HDIM;

    __shared__ float As[16][133];
    __shared__ float Bs[16][68];

    const int tid = threadIdx.x;
    const int tm = (tid >> 4) * 8;
    const int tn = (tid & 15) * 4;

    float acc[8][4] = {};

    const int kmax = (m0 + 128 < SQ) ? (m0 + 128) : SQ;
    for (int k0 = 0; k0 < kmax; k0 += 16) {
#pragma unroll
        for (int r = 0; r < 2; r++) {
            const int t    = tid + r * 256;
            const int row  = t >> 2;
            const int quad = (t & 3) * 4;
            float4 w4 = *(const float4*)(Wp + (size_t)(m0 + row) * SQ + k0 + quad);
            As[quad + 0][row] = w4.x; As[quad + 1][row] = w4.y;
            As[quad + 2][row] = w4.z; As[quad + 3][row] = w4.w;
        }
        {
            const int vr = tid >> 4;
            const int vc = (tid & 15) * 4;
            float4 v4 = *(const float4*)(Vp + (size_t)(k0 + vr) * EMB + vc);
            Bs[vr][vc + 0] = v4.x; Bs[vr][vc + 1] = v4.y;
            Bs[vr][vc + 2] = v4.z; Bs[vr][vc + 3] = v4.w;
        }
        __syncthreads();
#pragma unroll
        for (int kk = 0; kk < 16; kk++) {
            float bv[4];
#pragma unroll
            for (int j = 0; j < 4; j++) bv[j] = Bs[kk][tn + j];
#pragma unroll
            for (int i = 0; i < 8; i++) {
                const float a = As[kk][tm + i];
#pragma unroll
                for (int j = 0; j < 4; j++) acc[i][j] += a * bv[j];
            }
        }
        __syncthreads();
    }

#pragma unroll
    for (int i = 0; i < 8; i++) {
        *(float4*)(Op + (size_t)(m0 + tm + i) * EMB + tn) =
            make_float4(acc[i][0], acc[i][1], acc[i][2], acc[i][3]);
    }
}

// ---------------------------------------------------------------------------
// Launch
// ---------------------------------------------------------------------------
extern "C" void kernel_launch(void* const* d_in, const int* in_sizes, int n_in,
                              void* d_out, int out_size)
{
    const float* X  = (const float*)d_in[0];   // query  [B,S,E]
    const float* Wq = (const float*)d_in[3];
    const float* Wk = (const float*)d_in[4];
    const float* Wv = (const float*)d_in[5];
    const float* Wo = (const float*)d_in[6];
    float* out = (float*)d_out;

    float *Qp, *Kp, *Vp, *AOp, *SCp;
    __nv_bfloat16 *Xhi, *Xlo, *AOhi, *AOlo, *Whi, *Wlo;
    cudaGetSymbolAddress((void**)&Qp,   g_Q);
    cudaGetSymbolAddress((void**)&Kp,   g_K);
    cudaGetSymbolAddress((void**)&Vp,   g_V);
    cudaGetSymbolAddress((void**)&AOp,  g_AO);
    cudaGetSymbolAddress((void**)&SCp,  g_SC);
    cudaGetSymbolAddress((void**)&Xhi,  g_Xhi);
    cudaGetSymbolAddress((void**)&Xlo,  g_Xlo);
    cudaGetSymbolAddress((void**)&AOhi, g_AOhi);
    cudaGetSymbolAddress((void**)&AOlo, g_AOlo);
    cudaGetSymbolAddress((void**)&Whi,  g_Whi);
    cudaGetSymbolAddress((void**)&Wlo,  g_Wlo);

    const size_t n_attn = (size_t)MR * EMB;          // 4,194,304
    const size_t n_w    = (size_t)NB * NH * SQ * SQ; // 134,217,728

    float* attndst;
    float* wdst;
    if ((size_t)out_size >= n_attn + n_w) { attndst = out; wdst = out + n_attn; }
    else if ((size_t)out_size == n_w)     { attndst = nullptr; wdst = out; }
    else                                  { attndst = out; wdst = SCp; }

    const dim3 blk(256);
    const int WELEM = EMB * EMB;           // 1,048,576

    // hi/lo splits: X and the four weight matrices
    split_kernel<<<(MR * EMB / 4 + 255) / 256, blk>>>(X, Xhi, Xlo, MR * EMB / 4);
    split_kernel<<<(WELEM / 4 + 255) / 256, blk>>>(Wq, Whi + 0 * WELEM, Wlo + 0 * WELEM, WELEM / 4);
    split_kernel<<<(WELEM / 4 + 255) / 256, blk>>>(Wk, Whi + 1 * WELEM, Wlo + 1 * WELEM, WELEM / 4);
    split_kernel<<<(WELEM / 4 + 255) / 256, blk>>>(Wv, Whi + 2 * WELEM, Wlo + 2 * WELEM, WELEM / 4);
    split_kernel<<<(WELEM / 4 + 255) / 256, blk>>>(Wo, Whi + 3 * WELEM, Wlo + 3 * WELEM, WELEM / 4);

    // Q/K/V projections on tensor cores (3xBF16, fp32 accumulate)
    const dim3 ggrid(EMB / 128, MR / 128);
    mma_gemm<<<ggrid, blk>>>(Xhi, Xlo, Whi + 0 * WELEM, Wlo + 0 * WELEM, Qp);
    mma_gemm<<<ggrid, blk>>>(Xhi, Xlo, Whi + 1 * WELEM, Wlo + 1 * WELEM, Kp);
    mma_gemm<<<ggrid, blk>>>(Xhi, Xlo, Whi + 2 * WELEM, Wlo + 2 * WELEM, Vp);

    // raw scores straight into the weights destination (causal tiles only)
    scores_kernel<<<dim3(SQ / 128, SQ / 128, NB * NH), blk>>>(Qp, Kp, wdst);

    // softmax in-place on wdst (also zero-fills masked upper triangle)
    softmax_kernel<<<dim3(SQ, NB * NH), blk>>>(wdst, wdst);

    if (attndst) {
        av_kernel<<<dim3(SQ / 128, NB * NH), blk>>>(wdst, Vp, AOp);
        split_kernel<<<(MR * EMB / 4 + 255) / 256, blk>>>(AOp, AOhi, AOlo, MR * EMB / 4);
        mma_gemm<<<ggrid, blk>>>(AOhi, AOlo, Whi + 3 * WELEM, Wlo + 3 * WELEM, attndst);
    }
}